// round 10
// baseline (speedup 1.0000x reference)
#include <cuda_runtime.h>
#include <cuda_fp16.h>
#include <math.h>
#include <stdint.h>

#define BSZ 2
#define SEQ 2048
#define DIM 2048
#define NH  16
#define HD  128
#define MROWS (BSZ*SEQ)          // 4096

// ---------------- scratch (static device globals; no allocation) -----------
__device__ __half g_xh[(size_t)MROWS * DIM];
__device__ __half g_wqh[(size_t)DIM * DIM];
__device__ __half g_wkh[(size_t)DIM * DIM];
__device__ __half g_wvh[(size_t)DIM * DIM];
__device__ __half g_woh[(size_t)DIM * DIM];
__device__ __half g_ah[(size_t)MROWS * DIM];     // attention out [B,S,DIM]

// per-head fp16 Q,K,V  [B*NH, SEQ, HD]
#define HELEMS ((size_t)BSZ * NH * SEQ * HD)
__device__ __half g_Qh[HELEMS];
__device__ __half g_Kh[HELEMS];
__device__ __half g_Vh[HELEMS];

// ======================= helpers ==========================================
__device__ __forceinline__ uint32_t smem_u32(const void* p) {
    uint32_t a;
    asm("{ .reg .u64 t; cvta.to.shared.u64 t, %1; cvt.u32.u64 %0, t; }"
        : "=r"(a) : "l"(p));
    return a;
}
__device__ __forceinline__ void cp16(uint32_t saddr, const void* g) {
    asm volatile("cp.async.ca.shared.global [%0], [%1], 16;"
                 :: "r"(saddr), "l"(g));
}
#define CP_COMMIT() asm volatile("cp.async.commit_group;" ::: "memory")
#define CP_WAIT(n)  asm volatile("cp.async.wait_group %0;" :: "n"(n) : "memory")

__device__ __forceinline__ void ldm_x4(uint32_t* d, uint32_t addr) {
    asm volatile("ldmatrix.sync.aligned.m8n8.x4.shared.b16 {%0,%1,%2,%3}, [%4];"
                 : "=r"(d[0]), "=r"(d[1]), "=r"(d[2]), "=r"(d[3]) : "r"(addr));
}
__device__ __forceinline__ void ldm_x4t(uint32_t* d, uint32_t addr) {
    asm volatile("ldmatrix.sync.aligned.m8n8.x4.trans.shared.b16 {%0,%1,%2,%3}, [%4];"
                 : "=r"(d[0]), "=r"(d[1]), "=r"(d[2]), "=r"(d[3]) : "r"(addr));
}
__device__ __forceinline__ void mma_f16(float* c, const uint32_t* a,
                                        uint32_t b0, uint32_t b1) {
    asm volatile(
        "mma.sync.aligned.m16n8k16.row.col.f32.f16.f16.f32 "
        "{%0,%1,%2,%3}, {%4,%5,%6,%7}, {%8,%9}, {%0,%1,%2,%3};"
        : "+f"(c[0]), "+f"(c[1]), "+f"(c[2]), "+f"(c[3])
        : "r"(a[0]), "r"(a[1]), "r"(a[2]), "r"(a[3]), "r"(b0), "r"(b1));
}
// pack {lo, hi} floats -> f16x2 (lo in low half)
__device__ __forceinline__ uint32_t pk2(float lo, float hi) {
    uint32_t r;
    asm("cvt.rn.f16x2.f32 %0, %1, %2;" : "=r"(r) : "f"(hi), "f"(lo));
    return r;
}

// =================== convert fp32 -> fp16 ==================================
__global__ __launch_bounds__(256) void cvt_hi_kernel(
    const float4* __restrict__ in, uint32_t* __restrict__ hi, int n4)
{
    int i = blockIdx.x * blockDim.x + threadIdx.x;
    if (i >= n4) return;
    float4 v = in[i];
    hi[2 * i]     = pk2(v.x, v.y);
    hi[2 * i + 1] = pk2(v.z, v.w);
}

// all 4 weights in one launch (blockIdx.y selects the matrix)
__global__ __launch_bounds__(256) void cvt_w4_kernel(
    const float4* __restrict__ w0, const float4* __restrict__ w1,
    const float4* __restrict__ w2, const float4* __restrict__ w3,
    uint32_t* __restrict__ o0, uint32_t* __restrict__ o1,
    uint32_t* __restrict__ o2, uint32_t* __restrict__ o3, int n4)
{
    int i = blockIdx.x * blockDim.x + threadIdx.x;
    if (i >= n4) return;
    const float4* in; uint32_t* hi;
    switch (blockIdx.y) {
        case 0:  in = w0; hi = o0; break;
        case 1:  in = w1; hi = o1; break;
        case 2:  in = w2; hi = o2; break;
        default: in = w3; hi = o3; break;
    }
    float4 v = in[i];
    hi[2 * i]     = pk2(v.x, v.y);
    hi[2 * i + 1] = pk2(v.z, v.w);
}

// =============== mma.sync NT GEMM (1-pass fp16, fp32 accum) ================
// CTA tile 128x256, 8 warps, warp tile 64x64, BK=32, 2-stage cp.async.
// MODE 0: C fp32 [M, N]             (output projection -> d_out)
// MODE 1: rope + fp16 -> [B*H,S,HD] (Q/K projections)
// MODE 2: fp16 -> [B*H,S,HD]        (V projection)
#define GBM 128
#define GBN 256
#define GROWB 80                       // smem row stride in bytes (40 halves)
#define ATILEB (GBM * GROWB)           // 10240
#define BTILEB (GBN * GROWB)           // 20480
#define STAGEB (ATILEB + BTILEB)       // 30720
#define GEMM_SMEM (2 * STAGEB)         // 61440

__device__ __forceinline__ void gemm_load_chunk(
    uint32_t sbase,
    const __half* __restrict__ Ah, const __half* __restrict__ Bh,
    int row0, int col0, int k0, int tid)
{
#pragma unroll
    for (int i = 0; i < 2; ++i) {      // A: 128 rows x 64B
        int v = tid + i * 256;
        int r = v >> 2, cv = v & 3;
        uint32_t soff = (uint32_t)(r * GROWB + cv * 16);
        cp16(sbase + soff, Ah + (size_t)(row0 + r) * DIM + k0 + cv * 8);
    }
#pragma unroll
    for (int i = 0; i < 4; ++i) {      // B: 256 rows x 64B
        int v = tid + i * 256;
        int r = v >> 2, cv = v & 3;
        uint32_t soff = (uint32_t)(r * GROWB + cv * 16);
        cp16(sbase + ATILEB + soff, Bh + (size_t)(col0 + r) * DIM + k0 + cv * 8);
    }
}

template<int MODE>
__global__ __launch_bounds__(256, 1) void gemm_mma_kernel(
    const __half* __restrict__ Ah, const __half* __restrict__ Bh,
    float* __restrict__ C, uint32_t* __restrict__ O16,
    const float* __restrict__ cosT, const float* __restrict__ sinT)
{
    extern __shared__ char smem[];
    uint32_t sm0 = smem_u32(smem);

    const int tid  = threadIdx.x;
    const int wid  = tid >> 5;
    const int lane = tid & 31;
    const int wr = wid >> 2, wc = wid & 3;
    const int m0w = wr * 64, n0w = wc * 64;
    const int row0 = blockIdx.y * GBM;
    const int col0 = blockIdx.x * GBN;

    const int g  = lane >> 3;
    const int fr = (g & 1) * 8 + (lane & 7);
    const int fc = (g >> 1) * 8;

    float acc[4][8][4];
#pragma unroll
    for (int a = 0; a < 4; a++)
#pragma unroll
        for (int b = 0; b < 8; b++)
#pragma unroll
            for (int d = 0; d < 4; d++) acc[a][b][d] = 0.f;

    const int nchunk = DIM / 32;

    gemm_load_chunk(sm0, Ah, Bh, row0, col0, 0, tid);
    CP_COMMIT();

    for (int c = 0; c < nchunk; ++c) {
        if (c + 1 < nchunk) {
            gemm_load_chunk(sm0 + ((c + 1) & 1) * STAGEB, Ah, Bh,
                            row0, col0, (c + 1) * 32, tid);
            CP_COMMIT();
            CP_WAIT(1);
        } else {
            CP_WAIT(0);
        }
        __syncthreads();

        uint32_t sb = sm0 + (c & 1) * STAGEB;
#pragma unroll
        for (int ks = 0; ks < 2; ++ks) {
            const int kb = ks * 16;            // halves
            uint32_t bh4[4][4];
#pragma unroll
            for (int nt2 = 0; nt2 < 4; ++nt2) {
                uint32_t ba = sb + ATILEB +
                    (uint32_t)((n0w + nt2 * 16 + fr) * GROWB + (kb + fc) * 2);
                ldm_x4(bh4[nt2], ba);
            }
#pragma unroll
            for (int mt = 0; mt < 4; ++mt) {
                uint32_t aa = sb +
                    (uint32_t)((m0w + mt * 16 + fr) * GROWB + (kb + fc) * 2);
                uint32_t ah[4];
                ldm_x4(ah, aa);
#pragma unroll
                for (int nt = 0; nt < 8; ++nt) {
                    uint32_t b0 = bh4[nt >> 1][nt & 1];
                    uint32_t b1 = bh4[nt >> 1][2 + (nt & 1)];
                    mma_f16(acc[mt][nt], ah, b0, b1);
                }
            }
        }
        __syncthreads();
    }

    // ------------------------------ epilogue -------------------------------
#pragma unroll
    for (int mt = 0; mt < 4; ++mt) {
#pragma unroll
        for (int nt = 0; nt < 8; ++nt) {
            int r  = row0 + m0w + mt * 16 + (lane >> 2);
            int cc = col0 + n0w + nt * 8 + (lane & 3) * 2;
            if (MODE == 0) {
                float2 v0; v0.x = acc[mt][nt][0]; v0.y = acc[mt][nt][1];
                float2 v1; v1.x = acc[mt][nt][2]; v1.y = acc[mt][nt][3];
                *(float2*)&C[(size_t)r * DIM + cc] = v0;
                *(float2*)&C[(size_t)(r + 8) * DIM + cc] = v1;
            } else {
                const int h  = cc >> 7;          // head
                const int hc = cc & 127;         // col within head (even)
                const int d2 = hc >> 1;
#pragma unroll
                for (int rr = 0; rr < 2; ++rr) {
                    int row = r + rr * 8;
                    int b = row >> 11, s = row & (SEQ - 1);
                    float v0 = acc[mt][nt][2 * rr], v1 = acc[mt][nt][2 * rr + 1];
                    size_t dst = ((((size_t)(b * NH + h)) * SEQ + s) * HD + hc) >> 1;
                    if (MODE == 1) {
                        float co = cosT[s * (HD / 2) + d2];
                        float sn = sinT[s * (HD / 2) + d2];
                        O16[dst] = pk2(v0 * co - v1 * sn, v0 * sn + v1 * co);
                    } else {
                        O16[dst] = pk2(v0, v1);
                    }
                }
            }
        }
    }
}

// ============= Flash attention via mma.sync (1-pass fp16) ==================
// CTA: 128 q-rows, 8 warps x 16 rows. BKV=64. double-buffered K/V. 2 CTA/SM.
#define FQS   272                  // smem row stride in BYTES (136 halves)
#define FB_QH 0
#define FB_ST 34816                // 128*272
#define FSTG  34816                // 2 * 64*272 (K + V)
#define FB_KH 0
#define FB_VH 17408
#define FLASH_SMEM (FB_ST + 2 * FSTG)   // 104448

__global__ __launch_bounds__(256, 2) void flash_mma_kernel(
    const __half* __restrict__ Qh, const __half* __restrict__ Kh,
    const __half* __restrict__ Vh, uint32_t* __restrict__ outH)
{
    extern __shared__ char smem[];
    uint32_t s0 = smem_u32(smem);
    const int bh  = blockIdx.x;
    const int qt  = (int)gridDim.y - 1 - (int)blockIdx.y;   // big tiles first
    const int tid = threadIdx.x, wid = tid >> 5, lane = tid & 31;
    const int m0w = wid * 16;
    const int gg  = lane >> 3;
    const int fr  = (gg & 1) * 8 + (lane & 7);
    const int fc  = (gg >> 1) * 8;
    const int q0  = qt * 128;
    const size_t hoff = (size_t)bh * SEQ * HD;
    const float scale = 0.08838834764831845f;   // 1/sqrt(128)

    {
        const __half* gq_h = Qh + hoff + (size_t)q0 * HD;
#pragma unroll
        for (int i = 0; i < 8; i++) {
            int v = tid + (i << 8); int r = v >> 4, c = v & 15;
            uint32_t so = (uint32_t)(r * FQS + c * 16);
            cp16(s0 + FB_QH + so, gq_h + r * HD + c * 8);
        }
        uint32_t sb = s0 + FB_ST;
#pragma unroll
        for (int i = 0; i < 4; i++) {
            int v = tid + (i << 8); int r = v >> 4, c = v & 15;
            uint32_t so = (uint32_t)(r * FQS + c * 16);
            size_t go = hoff + r * HD + c * 8;
            cp16(sb + FB_KH + so, Kh + go);
            cp16(sb + FB_VH + so, Vh + go);
        }
    }
    CP_COMMIT();

    float O[16][4];
#pragma unroll
    for (int i = 0; i < 16; i++)
#pragma unroll
        for (int j = 0; j < 4; j++) O[i][j] = 0.f;
    float m0 = -1e30f, m1 = -1e30f, l0 = 0.f, l1 = 0.f;

    const int last  = 2 * qt + 1;
    const int r0g   = q0 + m0w + (lane >> 2);
    const int cbase = (lane & 3) * 2;

    for (int kt = 0; kt <= last; kt++) {
        const int stg = kt & 1;
        if (kt < last) {
            uint32_t sb = s0 + FB_ST + (stg ^ 1) * FSTG;
            size_t kvo = hoff + (size_t)(kt + 1) * 64 * HD;
#pragma unroll
            for (int i = 0; i < 4; i++) {
                int v = tid + (i << 8); int r = v >> 4, c = v & 15;
                uint32_t so = (uint32_t)(r * FQS + c * 16);
                size_t go = kvo + r * HD + c * 8;
                cp16(sb + FB_KH + so, Kh + go);
                cp16(sb + FB_VH + so, Vh + go);
            }
            CP_COMMIT();
            CP_WAIT(1);
        } else {
            CP_WAIT(0);
        }
        __syncthreads();

        uint32_t sb = s0 + FB_ST + stg * FSTG;

        // ---- S = Q K^T (1-pass) ----
        float Sv[8][4];
#pragma unroll
        for (int i = 0; i < 8; i++)
#pragma unroll
            for (int j = 0; j < 4; j++) Sv[i][j] = 0.f;

#pragma unroll
        for (int kk = 0; kk < 8; kk++) {
            uint32_t qoff = (uint32_t)((m0w + fr) * FQS + (kk * 16 + fc) * 2);
            uint32_t ah[4];
            ldm_x4(ah, s0 + FB_QH + qoff);
#pragma unroll
            for (int nt2 = 0; nt2 < 4; nt2++) {
                uint32_t koff = (uint32_t)((nt2 * 16 + fr) * FQS + (kk * 16 + fc) * 2);
                uint32_t bh4[4];
                ldm_x4(bh4, sb + FB_KH + koff);
                mma_f16(Sv[2 * nt2],     ah, bh4[0], bh4[2]);
                mma_f16(Sv[2 * nt2 + 1], ah, bh4[1], bh4[3]);
            }
        }

        // ---- scale + causal mask ----
        if (kt >= 2 * qt) {
#pragma unroll
            for (int nt = 0; nt < 8; nt++) {
                int c0 = kt * 64 + nt * 8 + cbase;
                Sv[nt][0] = (c0     > r0g)     ? -1e30f : Sv[nt][0] * scale;
                Sv[nt][1] = (c0 + 1 > r0g)     ? -1e30f : Sv[nt][1] * scale;
                Sv[nt][2] = (c0     > r0g + 8) ? -1e30f : Sv[nt][2] * scale;
                Sv[nt][3] = (c0 + 1 > r0g + 8) ? -1e30f : Sv[nt][3] * scale;
            }
        } else {
#pragma unroll
            for (int nt = 0; nt < 8; nt++)
#pragma unroll
                for (int j = 0; j < 4; j++) Sv[nt][j] *= scale;
        }

        // ---- online softmax (rows r0g and r0g+8, 4 lanes each) ----
        float mx0 = -1e30f, mx1 = -1e30f;
#pragma unroll
        for (int nt = 0; nt < 8; nt++) {
            mx0 = fmaxf(mx0, fmaxf(Sv[nt][0], Sv[nt][1]));
            mx1 = fmaxf(mx1, fmaxf(Sv[nt][2], Sv[nt][3]));
        }
        mx0 = fmaxf(mx0, __shfl_xor_sync(0xffffffffu, mx0, 1));
        mx0 = fmaxf(mx0, __shfl_xor_sync(0xffffffffu, mx0, 2));
        mx1 = fmaxf(mx1, __shfl_xor_sync(0xffffffffu, mx1, 1));
        mx1 = fmaxf(mx1, __shfl_xor_sync(0xffffffffu, mx1, 2));

        float mn0 = fmaxf(m0, mx0), mn1 = fmaxf(m1, mx1);
        float al0 = __expf(m0 - mn0), al1 = __expf(m1 - mn1);
        float sum0 = 0.f, sum1 = 0.f;
#pragma unroll
        for (int nt = 0; nt < 8; nt++) {
            Sv[nt][0] = __expf(Sv[nt][0] - mn0); sum0 += Sv[nt][0];
            Sv[nt][1] = __expf(Sv[nt][1] - mn0); sum0 += Sv[nt][1];
            Sv[nt][2] = __expf(Sv[nt][2] - mn1); sum1 += Sv[nt][2];
            Sv[nt][3] = __expf(Sv[nt][3] - mn1); sum1 += Sv[nt][3];
        }
        sum0 += __shfl_xor_sync(0xffffffffu, sum0, 1);
        sum0 += __shfl_xor_sync(0xffffffffu, sum0, 2);
        sum1 += __shfl_xor_sync(0xffffffffu, sum1, 1);
        sum1 += __shfl_xor_sync(0xffffffffu, sum1, 2);
        l0 = l0 * al0 + sum0; l1 = l1 * al1 + sum1;
        m0 = mn0; m1 = mn1;
#pragma unroll
        for (int nt = 0; nt < 16; nt++) {
            O[nt][0] *= al0; O[nt][1] *= al0;
            O[nt][2] *= al1; O[nt][3] *= al1;
        }

        // ---- O += P V (1-pass) ----
#pragma unroll
        for (int kk = 0; kk < 4; kk++) {
            uint32_t pah[4];
            pah[0] = pk2(Sv[2 * kk][0],     Sv[2 * kk][1]);
            pah[1] = pk2(Sv[2 * kk][2],     Sv[2 * kk][3]);
            pah[2] = pk2(Sv[2 * kk + 1][0], Sv[2 * kk + 1][1]);
            pah[3] = pk2(Sv[2 * kk + 1][2], Sv[2 * kk + 1][3]);
#pragma unroll
            for (int j = 0; j < 8; j++) {
                uint32_t vo = (uint32_t)((kk * 16 + fr) * FQS + (j * 16 + fc) * 2);
                uint32_t vh4[4];
                ldm_x4t(vh4, sb + FB_VH + vo);
                mma_f16(O[2 * j],     pah, vh4[0], vh4[1]);
                mma_f16(O[2 * j + 1], pah, vh4[2], vh4[3]);
            }
        }
        __syncthreads();
    }

    // ---- epilogue: normalize, store fp16 to [B,S,DIM] ----
    float inv0 = 1.f / l0, inv1 = 1.f / l1;
    const int b = bh >> 4, h = bh & 15;
    const int s_row = q0 + m0w + (lane >> 2);
#pragma unroll
    for (int nt = 0; nt < 16; nt++) {
        int col = h * HD + nt * 8 + cbase;
        {
            size_t o = (((size_t)(b * SEQ + s_row)) * DIM + col) >> 1;
            outH[o] = pk2(O[nt][0] * inv0, O[nt][1] * inv0);
        }
        {
            size_t o = (((size_t)(b * SEQ + s_row + 8)) * DIM + col) >> 1;
            outH[o] = pk2(O[nt][2] * inv1, O[nt][3] * inv1);
        }
    }
}

// ---------------------------------------------------------------------------
extern "C" void kernel_launch(void* const* d_in, const int* in_sizes, int n_in,
                              void* d_out, int out_size)
{
    const float* x    = (const float*)d_in[0];
    const float* wq   = (const float*)d_in[1];
    const float* wk   = (const float*)d_in[2];
    const float* wv   = (const float*)d_in[3];
    const float* wo   = (const float*)d_in[4];
    const float* fcos = (const float*)d_in[5];
    const float* fsin = (const float*)d_in[6];
    float* out = (float*)d_out;

    __half *xh, *wqh, *wkh, *wvh, *woh, *ah;
    cudaGetSymbolAddress((void**)&xh,  g_xh);
    cudaGetSymbolAddress((void**)&wqh, g_wqh);
    cudaGetSymbolAddress((void**)&wkh, g_wkh);
    cudaGetSymbolAddress((void**)&wvh, g_wvh);
    cudaGetSymbolAddress((void**)&woh, g_woh);
    cudaGetSymbolAddress((void**)&ah,  g_ah);

    __half *Qh, *Kh, *Vh;
    cudaGetSymbolAddress((void**)&Qh, g_Qh);
    cudaGetSymbolAddress((void**)&Kh, g_Kh);
    cudaGetSymbolAddress((void**)&Vh, g_Vh);

    cudaFuncSetAttribute(gemm_mma_kernel<0>,
                         cudaFuncAttributeMaxDynamicSharedMemorySize, GEMM_SMEM);
    cudaFuncSetAttribute(gemm_mma_kernel<1>,
                         cudaFuncAttributeMaxDynamicSharedMemorySize, GEMM_SMEM);
    cudaFuncSetAttribute(gemm_mma_kernel<2>,
                         cudaFuncAttributeMaxDynamicSharedMemorySize, GEMM_SMEM);
    cudaFuncSetAttribute(flash_mma_kernel,
                         cudaFuncAttributeMaxDynamicSharedMemorySize, FLASH_SMEM);

    const int nx4 = (MROWS * DIM) / 4;
    const int nw4 = (DIM * DIM) / 4;
    cvt_hi_kernel<<<(nx4 + 255) / 256, 256>>>((const float4*)x, (uint32_t*)xh, nx4);
    cvt_w4_kernel<<<dim3((nw4 + 255) / 256, 4), 256>>>(
        (const float4*)wq, (const float4*)wk, (const float4*)wv, (const float4*)wo,
        (uint32_t*)wqh, (uint32_t*)wkh, (uint32_t*)wvh, (uint32_t*)woh, nw4);

    dim3 gGrid(DIM / GBN, MROWS / GBM);   // (8, 32)
    // Q, K: fused rope epilogue -> per-head fp16
    gemm_mma_kernel<1><<<gGrid, 256, GEMM_SMEM>>>(xh, wqh, nullptr, (uint32_t*)Qh, fcos, fsin);
    gemm_mma_kernel<1><<<gGrid, 256, GEMM_SMEM>>>(xh, wkh, nullptr, (uint32_t*)Kh, fcos, fsin);
    // V: fp16 convert epilogue -> per-head fp16
    gemm_mma_kernel<2><<<gGrid, 256, GEMM_SMEM>>>(xh, wvh, nullptr, (uint32_t*)Vh, nullptr, nullptr);

    flash_mma_kernel<<<dim3(BSZ * NH, SEQ / 128), 256, FLASH_SMEM>>>(
        Qh, Kh, Vh, (uint32_t*)ah);

    // output projection -> fp32 d_out
    gemm_mma_kernel<0><<<gGrid, 256, GEMM_SMEM>>>(ah, woh, out, nullptr, nullptr, nullptr);
}

// round 11
// speedup vs baseline: 1.0672x; 1.0672x over previous
#include <cuda_runtime.h>
#include <cuda_fp16.h>
#include <math.h>
#include <stdint.h>

#define BSZ 2
#define SEQ 2048
#define DIM 2048
#define NH  16
#define HD  128
#define MROWS (BSZ*SEQ)          // 4096

// ---------------- scratch (static device globals; no allocation) -----------
__device__ __half g_xh[(size_t)MROWS * DIM];
__device__ __half g_wqkvh[(size_t)3 * DIM * DIM];   // [wq; wk; wv] rows
__device__ __half g_woh[(size_t)DIM * DIM];
__device__ __half g_ah[(size_t)MROWS * DIM];        // attention out [B,S,DIM]

// per-head fp16 Q,K,V  [B*NH, SEQ, HD]
#define HELEMS ((size_t)BSZ * NH * SEQ * HD)
__device__ __half g_Qh[HELEMS];
__device__ __half g_Kh[HELEMS];
__device__ __half g_Vh[HELEMS];

// ======================= helpers ==========================================
__device__ __forceinline__ uint32_t smem_u32(const void* p) {
    uint32_t a;
    asm("{ .reg .u64 t; cvta.to.shared.u64 t, %1; cvt.u32.u64 %0, t; }"
        : "=r"(a) : "l"(p));
    return a;
}
__device__ __forceinline__ void cp16(uint32_t saddr, const void* g) {
    asm volatile("cp.async.ca.shared.global [%0], [%1], 16;"
                 :: "r"(saddr), "l"(g));
}
#define CP_COMMIT() asm volatile("cp.async.commit_group;" ::: "memory")
#define CP_WAIT(n)  asm volatile("cp.async.wait_group %0;" :: "n"(n) : "memory")

__device__ __forceinline__ void ldm_x4(uint32_t* d, uint32_t addr) {
    asm volatile("ldmatrix.sync.aligned.m8n8.x4.shared.b16 {%0,%1,%2,%3}, [%4];"
                 : "=r"(d[0]), "=r"(d[1]), "=r"(d[2]), "=r"(d[3]) : "r"(addr));
}
__device__ __forceinline__ void ldm_x4t(uint32_t* d, uint32_t addr) {
    asm volatile("ldmatrix.sync.aligned.m8n8.x4.trans.shared.b16 {%0,%1,%2,%3}, [%4];"
                 : "=r"(d[0]), "=r"(d[1]), "=r"(d[2]), "=r"(d[3]) : "r"(addr));
}
__device__ __forceinline__ void mma_f16(float* c, const uint32_t* a,
                                        uint32_t b0, uint32_t b1) {
    asm volatile(
        "mma.sync.aligned.m16n8k16.row.col.f32.f16.f16.f32 "
        "{%0,%1,%2,%3}, {%4,%5,%6,%7}, {%8,%9}, {%0,%1,%2,%3};"
        : "+f"(c[0]), "+f"(c[1]), "+f"(c[2]), "+f"(c[3])
        : "r"(a[0]), "r"(a[1]), "r"(a[2]), "r"(a[3]), "r"(b0), "r"(b1));
}
// pack {lo, hi} floats -> f16x2 (lo in low half)
__device__ __forceinline__ uint32_t pk2(float lo, float hi) {
    uint32_t r;
    asm("cvt.rn.f16x2.f32 %0, %1, %2;" : "=r"(r) : "f"(hi), "f"(lo));
    return r;
}

// =================== convert fp32 -> fp16 ==================================
__global__ __launch_bounds__(256) void cvt_hi_kernel(
    const float4* __restrict__ in, uint32_t* __restrict__ hi, int n4)
{
    int i = blockIdx.x * blockDim.x + threadIdx.x;
    if (i >= n4) return;
    float4 v = in[i];
    hi[2 * i]     = pk2(v.x, v.y);
    hi[2 * i + 1] = pk2(v.z, v.w);
}

// all 4 weights in one launch (blockIdx.y selects the matrix)
__global__ __launch_bounds__(256) void cvt_w4_kernel(
    const float4* __restrict__ w0, const float4* __restrict__ w1,
    const float4* __restrict__ w2, const float4* __restrict__ w3,
    uint32_t* __restrict__ o0, uint32_t* __restrict__ o1,
    uint32_t* __restrict__ o2, uint32_t* __restrict__ o3, int n4)
{
    int i = blockIdx.x * blockDim.x + threadIdx.x;
    if (i >= n4) return;
    const float4* in; uint32_t* hi;
    switch (blockIdx.y) {
        case 0:  in = w0; hi = o0; break;
        case 1:  in = w1; hi = o1; break;
        case 2:  in = w2; hi = o2; break;
        default: in = w3; hi = o3; break;
    }
    float4 v = in[i];
    hi[2 * i]     = pk2(v.x, v.y);
    hi[2 * i + 1] = pk2(v.z, v.w);
}

// =============== mma.sync NT GEMM (1-pass fp16, fp32 accum) ================
// CTA tile 128x128, 8 warps (64x32 each), BK=32, 4-stage cp.async, 2 CTA/SM.
// MODE 0: C fp32 [M, DIM]                 (output projection -> d_out)
// MODE 1: fused QKV, N=3*DIM; rope for Q,K; fp16 per-head out
#define GROWB 80                       // smem row stride in bytes (40 halves)
#define TILEB (128 * GROWB)            // 10240 bytes per operand tile
#define STAGEB (2 * TILEB)             // A + B = 20480 bytes
#define NSTG 4
#define GEMM_SMEM (NSTG * STAGEB)      // 81920 bytes

__device__ __forceinline__ void gemm_load_chunk(
    uint32_t sbase,
    const __half* __restrict__ Ah, const __half* __restrict__ Bh,
    int row0, int col0, int k0, int tid)
{
#pragma unroll
    for (int i = 0; i < 2; ++i) {
        int v = tid + i * 256;
        int r = v >> 2, cv = v & 3;
        uint32_t soff = (uint32_t)(r * GROWB + cv * 16);
        cp16(sbase + soff,         Ah + (size_t)(row0 + r) * DIM + k0 + cv * 8);
        cp16(sbase + TILEB + soff, Bh + (size_t)(col0 + r) * DIM + k0 + cv * 8);
    }
}

template<int MODE>
__global__ __launch_bounds__(256, 2) void gemm_mma_kernel(
    const __half* __restrict__ Ah, const __half* __restrict__ Bh,
    float* __restrict__ C,
    uint32_t* __restrict__ Q16, uint32_t* __restrict__ K16,
    uint32_t* __restrict__ V16,
    const float* __restrict__ cosT, const float* __restrict__ sinT)
{
    extern __shared__ char smem[];
    uint32_t sm0 = smem_u32(smem);

    const int tid  = threadIdx.x;
    const int wid  = tid >> 5;
    const int lane = tid & 31;
    const int wr = wid >> 2, wc = wid & 3;
    const int m0w = wr * 64, n0w = wc * 32;
    const int row0 = blockIdx.y * 128;
    const int col0 = blockIdx.x * 128;

    const int g  = lane >> 3;
    const int fr = (g & 1) * 8 + (lane & 7);
    const int fc = (g >> 1) * 8;

    float acc[4][4][4];
#pragma unroll
    for (int a = 0; a < 4; a++)
#pragma unroll
        for (int b = 0; b < 4; b++)
#pragma unroll
            for (int d = 0; d < 4; d++) acc[a][b][d] = 0.f;

    const int nchunk = DIM / 32;   // 64

    // prefetch NSTG-1 stages
#pragma unroll
    for (int s = 0; s < NSTG - 1; ++s) {
        gemm_load_chunk(sm0 + s * STAGEB, Ah, Bh, row0, col0, s * 32, tid);
        CP_COMMIT();
    }

    for (int c = 0; c < nchunk; ++c) {
        if (c + NSTG - 1 < nchunk) {
            gemm_load_chunk(sm0 + ((c + NSTG - 1) & (NSTG - 1)) * STAGEB,
                            Ah, Bh, row0, col0, (c + NSTG - 1) * 32, tid);
            CP_COMMIT();
            CP_WAIT(NSTG - 1);
        } else {
            CP_WAIT(0);
        }
        __syncthreads();

        uint32_t sb = sm0 + (c & (NSTG - 1)) * STAGEB;
#pragma unroll
        for (int ks = 0; ks < 2; ++ks) {
            const int kb = ks * 16;            // halves
            uint32_t bh4[2][4];
#pragma unroll
            for (int nt2 = 0; nt2 < 2; ++nt2) {
                uint32_t ba = sb + TILEB +
                    (uint32_t)((n0w + nt2 * 16 + fr) * GROWB + (kb + fc) * 2);
                ldm_x4(bh4[nt2], ba);
            }
#pragma unroll
            for (int mt = 0; mt < 4; ++mt) {
                uint32_t aa = sb +
                    (uint32_t)((m0w + mt * 16 + fr) * GROWB + (kb + fc) * 2);
                uint32_t ah[4];
                ldm_x4(ah, aa);
#pragma unroll
                for (int nt = 0; nt < 4; ++nt) {
                    uint32_t b0 = bh4[nt >> 1][nt & 1];
                    uint32_t b1 = bh4[nt >> 1][2 + (nt & 1)];
                    mma_f16(acc[mt][nt], ah, b0, b1);
                }
            }
        }
        __syncthreads();
    }

    // ------------------------------ epilogue -------------------------------
    if (MODE == 0) {
#pragma unroll
        for (int mt = 0; mt < 4; ++mt) {
#pragma unroll
            for (int nt = 0; nt < 4; ++nt) {
                int r  = row0 + m0w + mt * 16 + (lane >> 2);
                int cc = col0 + n0w + nt * 8 + (lane & 3) * 2;
                float2 v0; v0.x = acc[mt][nt][0]; v0.y = acc[mt][nt][1];
                float2 v1; v1.x = acc[mt][nt][2]; v1.y = acc[mt][nt][3];
                *(float2*)&C[(size_t)r * DIM + cc] = v0;
                *(float2*)&C[(size_t)(r + 8) * DIM + cc] = v1;
            }
        }
    } else {
        const int matc = col0 >> 11;                 // 0=Q 1=K 2=V (uniform)
        uint32_t* obuf = (matc == 0) ? Q16 : (matc == 1) ? K16 : V16;
        const int mc0 = col0 & 2047;
#pragma unroll
        for (int mt = 0; mt < 4; ++mt) {
#pragma unroll
            for (int nt = 0; nt < 4; ++nt) {
                int r  = row0 + m0w + mt * 16 + (lane >> 2);
                int cc = mc0 + n0w + nt * 8 + (lane & 3) * 2;
                const int h  = cc >> 7;              // head
                const int hc = cc & 127;             // col within head (even)
                const int d2 = hc >> 1;
#pragma unroll
                for (int rr = 0; rr < 2; ++rr) {
                    int row = r + rr * 8;
                    int b = row >> 11, s = row & (SEQ - 1);
                    float v0 = acc[mt][nt][2 * rr], v1 = acc[mt][nt][2 * rr + 1];
                    size_t dst = ((((size_t)(b * NH + h)) * SEQ + s) * HD + hc) >> 1;
                    if (matc < 2) {
                        float co = cosT[s * (HD / 2) + d2];
                        float sn = sinT[s * (HD / 2) + d2];
                        obuf[dst] = pk2(v0 * co - v1 * sn, v0 * sn + v1 * co);
                    } else {
                        obuf[dst] = pk2(v0, v1);
                    }
                }
            }
        }
    }
}

// ============= Flash attention via mma.sync (1-pass fp16) ==================
// CTA: 128 q-rows, 8 warps x 16 rows. BKV=64. double-buffered K/V. 2 CTA/SM.
#define FQS   272                  // smem row stride in BYTES (136 halves)
#define FB_QH 0
#define FB_ST 34816                // 128*272
#define FSTG  34816                // 2 * 64*272 (K + V)
#define FB_KH 0
#define FB_VH 17408
#define FLASH_SMEM (FB_ST + 2 * FSTG)   // 104448

__global__ __launch_bounds__(256, 2) void flash_mma_kernel(
    const __half* __restrict__ Qh, const __half* __restrict__ Kh,
    const __half* __restrict__ Vh, uint32_t* __restrict__ outH)
{
    extern __shared__ char smem[];
    uint32_t s0 = smem_u32(smem);
    const int bh  = blockIdx.x;
    const int qt  = (int)gridDim.y - 1 - (int)blockIdx.y;   // big tiles first
    const int tid = threadIdx.x, wid = tid >> 5, lane = tid & 31;
    const int m0w = wid * 16;
    const int gg  = lane >> 3;
    const int fr  = (gg & 1) * 8 + (lane & 7);
    const int fc  = (gg >> 1) * 8;
    const int q0  = qt * 128;
    const size_t hoff = (size_t)bh * SEQ * HD;
    const float scale = 0.08838834764831845f;   // 1/sqrt(128)

    {
        const __half* gq_h = Qh + hoff + (size_t)q0 * HD;
#pragma unroll
        for (int i = 0; i < 8; i++) {
            int v = tid + (i << 8); int r = v >> 4, c = v & 15;
            uint32_t so = (uint32_t)(r * FQS + c * 16);
            cp16(s0 + FB_QH + so, gq_h + r * HD + c * 8);
        }
        uint32_t sb = s0 + FB_ST;
#pragma unroll
        for (int i = 0; i < 4; i++) {
            int v = tid + (i << 8); int r = v >> 4, c = v & 15;
            uint32_t so = (uint32_t)(r * FQS + c * 16);
            size_t go = hoff + r * HD + c * 8;
            cp16(sb + FB_KH + so, Kh + go);
            cp16(sb + FB_VH + so, Vh + go);
        }
    }
    CP_COMMIT();

    float O[16][4];
#pragma unroll
    for (int i = 0; i < 16; i++)
#pragma unroll
        for (int j = 0; j < 4; j++) O[i][j] = 0.f;
    float m0 = -1e30f, m1 = -1e30f, l0 = 0.f, l1 = 0.f;

    const int last  = 2 * qt + 1;
    const int r0g   = q0 + m0w + (lane >> 2);
    const int cbase = (lane & 3) * 2;

    for (int kt = 0; kt <= last; kt++) {
        const int stg = kt & 1;
        if (kt < last) {
            uint32_t sb = s0 + FB_ST + (stg ^ 1) * FSTG;
            size_t kvo = hoff + (size_t)(kt + 1) * 64 * HD;
#pragma unroll
            for (int i = 0; i < 4; i++) {
                int v = tid + (i << 8); int r = v >> 4, c = v & 15;
                uint32_t so = (uint32_t)(r * FQS + c * 16);
                size_t go = kvo + r * HD + c * 8;
                cp16(sb + FB_KH + so, Kh + go);
                cp16(sb + FB_VH + so, Vh + go);
            }
            CP_COMMIT();
            CP_WAIT(1);
        } else {
            CP_WAIT(0);
        }
        __syncthreads();

        uint32_t sb = s0 + FB_ST + stg * FSTG;

        // ---- S = Q K^T (1-pass) ----
        float Sv[8][4];
#pragma unroll
        for (int i = 0; i < 8; i++)
#pragma unroll
            for (int j = 0; j < 4; j++) Sv[i][j] = 0.f;

#pragma unroll
        for (int kk = 0; kk < 8; kk++) {
            uint32_t qoff = (uint32_t)((m0w + fr) * FQS + (kk * 16 + fc) * 2);
            uint32_t ah[4];
            ldm_x4(ah, s0 + FB_QH + qoff);
#pragma unroll
            for (int nt2 = 0; nt2 < 4; nt2++) {
                uint32_t koff = (uint32_t)((nt2 * 16 + fr) * FQS + (kk * 16 + fc) * 2);
                uint32_t bh4[4];
                ldm_x4(bh4, sb + FB_KH + koff);
                mma_f16(Sv[2 * nt2],     ah, bh4[0], bh4[2]);
                mma_f16(Sv[2 * nt2 + 1], ah, bh4[1], bh4[3]);
            }
        }

        // ---- scale + causal mask ----
        if (kt >= 2 * qt) {
#pragma unroll
            for (int nt = 0; nt < 8; nt++) {
                int c0 = kt * 64 + nt * 8 + cbase;
                Sv[nt][0] = (c0     > r0g)     ? -1e30f : Sv[nt][0] * scale;
                Sv[nt][1] = (c0 + 1 > r0g)     ? -1e30f : Sv[nt][1] * scale;
                Sv[nt][2] = (c0     > r0g + 8) ? -1e30f : Sv[nt][2] * scale;
                Sv[nt][3] = (c0 + 1 > r0g + 8) ? -1e30f : Sv[nt][3] * scale;
            }
        } else {
#pragma unroll
            for (int nt = 0; nt < 8; nt++)
#pragma unroll
                for (int j = 0; j < 4; j++) Sv[nt][j] *= scale;
        }

        // ---- online softmax ----
        float mx0 = -1e30f, mx1 = -1e30f;
#pragma unroll
        for (int nt = 0; nt < 8; nt++) {
            mx0 = fmaxf(mx0, fmaxf(Sv[nt][0], Sv[nt][1]));
            mx1 = fmaxf(mx1, fmaxf(Sv[nt][2], Sv[nt][3]));
        }
        mx0 = fmaxf(mx0, __shfl_xor_sync(0xffffffffu, mx0, 1));
        mx0 = fmaxf(mx0, __shfl_xor_sync(0xffffffffu, mx0, 2));
        mx1 = fmaxf(mx1, __shfl_xor_sync(0xffffffffu, mx1, 1));
        mx1 = fmaxf(mx1, __shfl_xor_sync(0xffffffffu, mx1, 2));

        float mn0 = fmaxf(m0, mx0), mn1 = fmaxf(m1, mx1);
        float al0 = __expf(m0 - mn0), al1 = __expf(m1 - mn1);
        float sum0 = 0.f, sum1 = 0.f;
#pragma unroll
        for (int nt = 0; nt < 8; nt++) {
            Sv[nt][0] = __expf(Sv[nt][0] - mn0); sum0 += Sv[nt][0];
            Sv[nt][1] = __expf(Sv[nt][1] - mn0); sum0 += Sv[nt][1];
            Sv[nt][2] = __expf(Sv[nt][2] - mn1); sum1 += Sv[nt][2];
            Sv[nt][3] = __expf(Sv[nt][3] - mn1); sum1 += Sv[nt][3];
        }
        sum0 += __shfl_xor_sync(0xffffffffu, sum0, 1);
        sum0 += __shfl_xor_sync(0xffffffffu, sum0, 2);
        sum1 += __shfl_xor_sync(0xffffffffu, sum1, 1);
        sum1 += __shfl_xor_sync(0xffffffffu, sum1, 2);
        l0 = l0 * al0 + sum0; l1 = l1 * al1 + sum1;
        m0 = mn0; m1 = mn1;
#pragma unroll
        for (int nt = 0; nt < 16; nt++) {
            O[nt][0] *= al0; O[nt][1] *= al0;
            O[nt][2] *= al1; O[nt][3] *= al1;
        }

        // ---- O += P V (1-pass) ----
#pragma unroll
        for (int kk = 0; kk < 4; kk++) {
            uint32_t pah[4];
            pah[0] = pk2(Sv[2 * kk][0],     Sv[2 * kk][1]);
            pah[1] = pk2(Sv[2 * kk][2],     Sv[2 * kk][3]);
            pah[2] = pk2(Sv[2 * kk + 1][0], Sv[2 * kk + 1][1]);
            pah[3] = pk2(Sv[2 * kk + 1][2], Sv[2 * kk + 1][3]);
#pragma unroll
            for (int j = 0; j < 8; j++) {
                uint32_t vo = (uint32_t)((kk * 16 + fr) * FQS + (j * 16 + fc) * 2);
                uint32_t vh4[4];
                ldm_x4t(vh4, sb + FB_VH + vo);
                mma_f16(O[2 * j],     pah, vh4[0], vh4[1]);
                mma_f16(O[2 * j + 1], pah, vh4[2], vh4[3]);
            }
        }
        __syncthreads();
    }

    // ---- epilogue: normalize, store fp16 to [B,S,DIM] ----
    float inv0 = 1.f / l0, inv1 = 1.f / l1;
    const int b = bh >> 4, h = bh & 15;
    const int s_row = q0 + m0w + (lane >> 2);
#pragma unroll
    for (int nt = 0; nt < 16; nt++) {
        int col = h * HD + nt * 8 + cbase;
        {
            size_t o = (((size_t)(b * SEQ + s_row)) * DIM + col) >> 1;
            outH[o] = pk2(O[nt][0] * inv0, O[nt][1] * inv0);
        }
        {
            size_t o = (((size_t)(b * SEQ + s_row + 8)) * DIM + col) >> 1;
            outH[o] = pk2(O[nt][2] * inv1, O[nt][3] * inv1);
        }
    }
}

// ---------------------------------------------------------------------------
extern "C" void kernel_launch(void* const* d_in, const int* in_sizes, int n_in,
                              void* d_out, int out_size)
{
    const float* x    = (const float*)d_in[0];
    const float* wq   = (const float*)d_in[1];
    const float* wk   = (const float*)d_in[2];
    const float* wv   = (const float*)d_in[3];
    const float* wo   = (const float*)d_in[4];
    const float* fcos = (const float*)d_in[5];
    const float* fsin = (const float*)d_in[6];
    float* out = (float*)d_out;

    __half *xh, *wqkvh, *woh, *ah;
    cudaGetSymbolAddress((void**)&xh,    g_xh);
    cudaGetSymbolAddress((void**)&wqkvh, g_wqkvh);
    cudaGetSymbolAddress((void**)&woh,   g_woh);
    cudaGetSymbolAddress((void**)&ah,    g_ah);

    __half *Qh, *Kh, *Vh;
    cudaGetSymbolAddress((void**)&Qh, g_Qh);
    cudaGetSymbolAddress((void**)&Kh, g_Kh);
    cudaGetSymbolAddress((void**)&Vh, g_Vh);

    cudaFuncSetAttribute(gemm_mma_kernel<0>,
                         cudaFuncAttributeMaxDynamicSharedMemorySize, GEMM_SMEM);
    cudaFuncSetAttribute(gemm_mma_kernel<1>,
                         cudaFuncAttributeMaxDynamicSharedMemorySize, GEMM_SMEM);
    cudaFuncSetAttribute(flash_mma_kernel,
                         cudaFuncAttributeMaxDynamicSharedMemorySize, FLASH_SMEM);

    const int nx4 = (MROWS * DIM) / 4;
    const int nw4 = (DIM * DIM) / 4;
    const size_t wsz = (size_t)DIM * DIM;
    cvt_hi_kernel<<<(nx4 + 255) / 256, 256>>>((const float4*)x, (uint32_t*)xh, nx4);
    cvt_w4_kernel<<<dim3((nw4 + 255) / 256, 4), 256>>>(
        (const float4*)wq, (const float4*)wk, (const float4*)wv, (const float4*)wo,
        (uint32_t*)wqkvh, (uint32_t*)(wqkvh + wsz), (uint32_t*)(wqkvh + 2 * wsz),
        (uint32_t*)woh, nw4);

    // fused QKV projection: N = 3*DIM, rope in epilogue for Q,K
    gemm_mma_kernel<1><<<dim3(3 * DIM / 128, MROWS / 128), 256, GEMM_SMEM>>>(
        xh, wqkvh, nullptr, (uint32_t*)Qh, (uint32_t*)Kh, (uint32_t*)Vh,
        fcos, fsin);

    flash_mma_kernel<<<dim3(BSZ * NH, SEQ / 128), 256, FLASH_SMEM>>>(
        Qh, Kh, Vh, (uint32_t*)ah);

    // output projection -> fp32 d_out
    gemm_mma_kernel<0><<<dim3(DIM / 128, MROWS / 128), 256, GEMM_SMEM>>>(
        ah, woh, out, nullptr, nullptr, nullptr, nullptr, nullptr);
}